// round 14
// baseline (speedup 1.0000x reference)
#include <cuda_runtime.h>
#include <cuda_bf16.h>
#include <cstdint>
#include <cstddef>

#define N_NODES 100000
#define DIM 128
#define N_REL 2
#define N_EDGES 500000
#define NB2 (N_REL * N_NODES)
#define CAP 64
#define MT ((N_NODES + 127) / 128)   // 782 M-tiles

// group slot: Ahi|Alo|Whi|Wlo, each 128 rows x 32 cols bf16, row stride 40 elems (80B, 16B-aligned)
#define SKC 40
#define TILE_E (128 * SKC)                    // 5120 elems = 10240 B per tile
#define SLOT_B (4 * TILE_E * 2)               // 40960 B per group slot
#define NSLOT 2
#define SMEM_BYTES (NSLOT * SLOT_B)           // 81920 B -> 2 CTA/SM

// ---------------- scratch ----------------
__device__ int g_cnti[NB2];
__device__ int g_bkt[(size_t)NB2 * CAP];
__device__ __nv_bfloat16 g_whi[6 * DIM * DIM];          // [w][n][k] transposed, split
__device__ __nv_bfloat16 g_wlo[6 * DIM * DIM];
__device__ __nv_bfloat16 g_xhi[(size_t)N_NODES * DIM];  // x planes; reused for relu(h2)
__device__ __nv_bfloat16 g_xlo[(size_t)N_NODES * DIM];
__device__ __nv_bfloat16 g_hhi[(size_t)N_NODES * DIM];  // relu(h1) planes
__device__ __nv_bfloat16 g_hlo[(size_t)N_NODES * DIM];
__device__ __nv_bfloat16 g_s0hi[(size_t)N_NODES * DIM];
__device__ __nv_bfloat16 g_s0lo[(size_t)N_NODES * DIM];
__device__ __nv_bfloat16 g_s1hi[(size_t)N_NODES * DIM];
__device__ __nv_bfloat16 g_s1lo[(size_t)N_NODES * DIM];

// ---------------- helpers ----------------
__device__ __forceinline__ uint32_t smem_u32(const void* p) {
    uint32_t a;
    asm("{ .reg .u64 t; cvta.to.shared.u64 t, %1; cvt.u32.u64 %0, t; }" : "=r"(a) : "l"(p));
    return a;
}
__device__ __forceinline__ void ldsm_x4(uint32_t* r, uint32_t addr) {
    asm volatile("ldmatrix.sync.aligned.m8n8.x4.shared.b16 {%0,%1,%2,%3}, [%4];"
                 : "=r"(r[0]), "=r"(r[1]), "=r"(r[2]), "=r"(r[3]) : "r"(addr));
}
__device__ __forceinline__ void mma16816(float* c, const uint32_t* a, uint32_t b0, uint32_t b1) {
    asm volatile("mma.sync.aligned.m16n8k16.row.col.f32.bf16.bf16.f32 "
                 "{%0,%1,%2,%3}, {%4,%5,%6,%7}, {%8,%9}, {%0,%1,%2,%3};"
                 : "+f"(c[0]), "+f"(c[1]), "+f"(c[2]), "+f"(c[3])
                 : "r"(a[0]), "r"(a[1]), "r"(a[2]), "r"(a[3]), "r"(b0), "r"(b1));
}
__device__ __forceinline__ void cp8(uint32_t dst, const void* src) {
    asm volatile("cp.async.ca.shared.global [%0], [%1], 8;" :: "r"(dst), "l"(src));
}
#define CP_COMMIT()  asm volatile("cp.async.commit_group;" ::: "memory")
#define CP_WAIT_1()  asm volatile("cp.async.wait_group 1;" ::: "memory")
#define CP_WAIT_0()  asm volatile("cp.async.wait_group 0;" ::: "memory")

__device__ __forceinline__ void split2(float a, float b, uint32_t& hi, uint32_t& lo) {
    __nv_bfloat16 ha = __float2bfloat16(a), hb = __float2bfloat16(b);
    __nv_bfloat16 la = __float2bfloat16(a - __bfloat162float(ha));
    __nv_bfloat16 lb = __float2bfloat16(b - __bfloat162float(hb));
    hi = (uint32_t)__bfloat16_as_ushort(ha) | ((uint32_t)__bfloat16_as_ushort(hb) << 16);
    lo = (uint32_t)__bfloat16_as_ushort(la) | ((uint32_t)__bfloat16_as_ushort(lb) << 16);
}
__device__ __forceinline__ float2 b22f(uint32_t u) {
    __nv_bfloat162 b = *reinterpret_cast<__nv_bfloat162*>(&u);
    return __bfloat1622float2(b);
}

// ---------------- CSR zero ----------------
__global__ void zero_cnt_k() {
    int i = blockIdx.x * blockDim.x + threadIdx.x;
    if (i < NB2) g_cnti[i] = 0;
}

// ---------------- fused: edge placement + weight/x split conversion ----------
#define CONV_TOTAL (6 * DIM * DIM + N_NODES * DIM)
__global__ void placeconv_k(const int* __restrict__ ei, const int* __restrict__ et,
                            const float* __restrict__ x,
                            const float* __restrict__ Wroot1, const float* __restrict__ Wrel1,
                            const float* __restrict__ Wroot2, const float* __restrict__ Wrel2) {
    int id = blockIdx.x * blockDim.x + threadIdx.x;
    if (id < N_EDGES) {
        int src = ei[id];
        int dst = ei[N_EDGES + id];
        int r = et[id];
        int idx = r * N_NODES + dst;
        int pos = atomicAdd(&g_cnti[idx], 1);
        if (pos < CAP) g_bkt[(size_t)idx * CAP + pos] = src;
    }
    if (id < 6 * DIM * DIM) {
        int w = id >> 14;
        int rem = id & 16383;
        int k = rem >> 7, n = rem & 127;
        float v;
        switch (w) {
            case 0: v = Wroot1[rem]; break;
            case 1: v = Wrel1[rem]; break;
            case 2: v = Wrel1[DIM * DIM + rem]; break;
            case 3: v = Wroot2[rem]; break;
            case 4: v = Wrel2[rem]; break;
            default: v = Wrel2[DIM * DIM + rem]; break;
        }
        __nv_bfloat16 hi = __float2bfloat16(v);
        __nv_bfloat16 lo = __float2bfloat16(v - __bfloat162float(hi));
        size_t dst = (size_t)w * DIM * DIM + (size_t)n * DIM + k;   // transposed [n][k]
        g_whi[dst] = hi;
        g_wlo[dst] = lo;
    }
    size_t id2 = (size_t)id - 6 * DIM * DIM;
    if (id >= 6 * DIM * DIM && id2 < (size_t)N_NODES * DIM) {
        float v = x[id2];
        __nv_bfloat16 hi = __float2bfloat16(v);
        __nv_bfloat16 lo = __float2bfloat16(v - __bfloat162float(hi));
        g_xhi[id2] = hi;
        g_xlo[id2] = lo;
    }
}

// ---------------- pre-aggregation: s_r = mean_r(features), split-bf16 out ----
// 4-wide unrolled gathers for MLP.
__global__ void __launch_bounds__(256)
agg_k(const float* __restrict__ xf, int layer)
{
    int gw = (blockIdx.x * blockDim.x + threadIdx.x) >> 5;
    if (gw >= N_NODES) return;
    int lane = threadIdx.x & 31;

#pragma unroll
    for (int r = 0; r < 2; r++) {
        int idx = r * N_NODES + gw;
        int cnt = g_cnti[idx];
        int n = min(cnt, CAP);
        const int* bkt = g_bkt + (size_t)idx * CAP;
        float s0 = 0.f, s1 = 0.f, s2 = 0.f, s3 = 0.f;
        if (layer == 0) {
            for (int j = 0; j < n; j += 4) {
                float4 t0 = make_float4(0.f, 0.f, 0.f, 0.f), t1 = t0, t2 = t0, t3 = t0;
                // independent gathers -> MLP 4
                if (j + 0 < n) t0 = ((const float4*)(xf + (size_t)__ldg(bkt + j + 0) * DIM))[lane];
                if (j + 1 < n) t1 = ((const float4*)(xf + (size_t)__ldg(bkt + j + 1) * DIM))[lane];
                if (j + 2 < n) t2 = ((const float4*)(xf + (size_t)__ldg(bkt + j + 2) * DIM))[lane];
                if (j + 3 < n) t3 = ((const float4*)(xf + (size_t)__ldg(bkt + j + 3) * DIM))[lane];
                s0 += (t0.x + t1.x) + (t2.x + t3.x);
                s1 += (t0.y + t1.y) + (t2.y + t3.y);
                s2 += (t0.z + t1.z) + (t2.z + t3.z);
                s3 += (t0.w + t1.w) + (t2.w + t3.w);
            }
        } else {
            for (int j = 0; j < n; j += 4) {
                uint2 h[4], l[4];
#pragma unroll
                for (int q = 0; q < 4; q++) { h[q] = make_uint2(0u, 0u); l[q] = make_uint2(0u, 0u); }
                if (j + 0 < n) { size_t a = (size_t)__ldg(bkt + j + 0) * DIM;
                    h[0] = ((const uint2*)(g_hhi + a))[lane]; l[0] = ((const uint2*)(g_hlo + a))[lane]; }
                if (j + 1 < n) { size_t a = (size_t)__ldg(bkt + j + 1) * DIM;
                    h[1] = ((const uint2*)(g_hhi + a))[lane]; l[1] = ((const uint2*)(g_hlo + a))[lane]; }
                if (j + 2 < n) { size_t a = (size_t)__ldg(bkt + j + 2) * DIM;
                    h[2] = ((const uint2*)(g_hhi + a))[lane]; l[2] = ((const uint2*)(g_hlo + a))[lane]; }
                if (j + 3 < n) { size_t a = (size_t)__ldg(bkt + j + 3) * DIM;
                    h[3] = ((const uint2*)(g_hhi + a))[lane]; l[3] = ((const uint2*)(g_hlo + a))[lane]; }
#pragma unroll
                for (int q = 0; q < 4; q++) {
                    float2 p1 = b22f(h[q].x), p2 = b22f(l[q].x);
                    s0 += p1.x + p2.x; s1 += p1.y + p2.y;
                    p1 = b22f(h[q].y); p2 = b22f(l[q].y);
                    s2 += p1.x + p2.x; s3 += p1.y + p2.y;
                }
            }
        }
        float w = cnt ? (1.0f / (float)cnt) : 0.0f;
        uint32_t h01, l01, h23, l23;
        split2(s0 * w, s1 * w, h01, l01);
        split2(s2 * w, s3 * w, h23, l23);
        __nv_bfloat16* shi = r ? g_s1hi : g_s0hi;
        __nv_bfloat16* slo = r ? g_s1lo : g_s0lo;
        ((uint2*)(shi + (size_t)gw * DIM))[lane] = make_uint2(h01, h23);
        ((uint2*)(slo + (size_t)gw * DIM))[lane] = make_uint2(l01, l23);
    }
}

// ---------------- grouped HMMA GEMM: 12 groups of (Ahi,Alo,Whi,Wlo) @ K=32 ---
// h = x@Wroot + s0@W0 + s1@W1 + b with split-bf16: per group all 3 products
// computed from register-held fragments; wlo ldsm hidden under MMA batch.
// 2-slot double buffer, M-tile 128, 256 thr, 8 warps, warp tile 32x64, 2 CTA/SM.
__global__ void __launch_bounds__(256, 2)
gemm12_k(const float* __restrict__ biasp, int layer)
{
    extern __shared__ __nv_bfloat16 sm[];
    const int tid = threadIdx.x;
    const int wid = tid >> 5;
    const int lane = tid & 31;
    const int wm = wid & 3;      // 4 warp rows x 32
    const int wn = wid >> 2;     // 2 warp cols x 64
    const int m0 = blockIdx.x * 128;

    const uint32_t sb = smem_u32(sm);

    const __nv_bfloat16* AHI[3] = { layer ? g_hhi : g_xhi, g_s0hi, g_s1hi };
    const __nv_bfloat16* ALO[3] = { layer ? g_hlo : g_xlo, g_s0lo, g_s1lo };
    const __nv_bfloat16* WH = g_whi + (size_t)(layer * 3) * DIM * DIM;
    const __nv_bfloat16* WL = g_wlo + (size_t)(layer * 3) * DIM * DIM;
    __nv_bfloat16* OH = layer ? g_xhi : g_hhi;
    __nv_bfloat16* OL = layer ? g_xlo : g_hlo;

    // group g: input i = g>>2, K-chunk kc = g&3 (K offset kc*32)
    auto loadGroup = [&](int g, int slot) {
        const int i = g >> 2;
        const int ko = (g & 3) * 32;
        const __nv_bfloat16* pah = AHI[i];
        const __nv_bfloat16* pal = ALO[i];
        const __nv_bfloat16* pwh = WH + (size_t)i * DIM * DIM;
        const __nv_bfloat16* pwl = WL + (size_t)i * DIM * DIM;
        const uint32_t base = sb + (uint32_t)slot * SLOT_B;
#pragma unroll
        for (int it = 0; it < 4; it++) {
            int idx = tid + it * 256;        // 1024: row = idx>>3, c4 = idx&7
            int row = idx >> 3, c4 = idx & 7;
            uint32_t doff = (uint32_t)(row * SKC + c4 * 4) * 2;
            size_t goff = (size_t)row * DIM + ko + c4 * 4;
            int gm = m0 + row;
            if (gm < N_NODES) {
                size_t aoffg = (size_t)gm * DIM + ko + c4 * 4;
                cp8(base + doff, pah + aoffg);
                cp8(base + (uint32_t)TILE_E * 2 + doff, pal + aoffg);
            }
            cp8(base + (uint32_t)TILE_E * 4 + doff, pwh + goff);
            cp8(base + (uint32_t)TILE_E * 6 + doff, pwl + goff);
        }
    };

    // prologue: groups 0, 1
    loadGroup(0, 0); CP_COMMIT();
    loadGroup(1, 1); CP_COMMIT();

    // per-lane ldmatrix offsets (validated layout; smem row stride SKC=40 elems = 80B)
    const int a_r = lane & 15;
    const int a_c = (lane >> 4) << 3;
    const int b_r = (lane & 7) + ((lane >> 4) << 3);
    const int b_c = ((lane >> 3) & 1) << 3;
    const uint32_t aoff = (uint32_t)((wm * 32 + a_r) * SKC + a_c) * 2;
    const uint32_t boff = (uint32_t)((wn * 64 + b_r) * SKC + b_c) * 2;

    float acc[2][8][4] = {};

#pragma unroll 1
    for (int g = 0; g < 12; g++) {
        if (g == 11) { CP_WAIT_0(); } else { CP_WAIT_1(); }
        __syncthreads();             // group g resident; other slot fully consumed

        const uint32_t base = sb + (uint32_t)(g & 1) * SLOT_B;
        const uint32_t sAhi = base;
        const uint32_t sAlo = base + (uint32_t)TILE_E * 2;
        const uint32_t sWhi = base + (uint32_t)TILE_E * 4;
        const uint32_t sWlo = base + (uint32_t)TILE_E * 6;

#pragma unroll
        for (int t = 0; t < 2; t++) {
            const uint32_t k2 = (uint32_t)t * 32;   // 16 elems = 32B per kstep
            uint32_t ah[2][4], al[2][4], wh[4][4], wl[4][4];
            ldsm_x4(ah[0], sAhi + aoff + k2);
            ldsm_x4(ah[1], sAhi + aoff + (uint32_t)(16 * SKC) * 2 + k2);
            ldsm_x4(al[0], sAlo + aoff + k2);
            ldsm_x4(al[1], sAlo + aoff + (uint32_t)(16 * SKC) * 2 + k2);
#pragma unroll
            for (int nt = 0; nt < 4; nt++)
                ldsm_x4(wh[nt], sWhi + boff + (uint32_t)(nt * 16 * SKC) * 2 + k2);
            // batch 1: Ahi x Whi (covers nothing; feeds pipe)
#pragma unroll
            for (int tm = 0; tm < 2; tm++)
#pragma unroll
                for (int nt = 0; nt < 4; nt++) {
                    mma16816(acc[tm][nt * 2 + 0], ah[tm], wh[nt][0], wh[nt][1]);
                    mma16816(acc[tm][nt * 2 + 1], ah[tm], wh[nt][2], wh[nt][3]);
                }
            // wlo ldsm issued here; latency hidden under batch 2
#pragma unroll
            for (int nt = 0; nt < 4; nt++)
                ldsm_x4(wl[nt], sWlo + boff + (uint32_t)(nt * 16 * SKC) * 2 + k2);
            // batch 2: Alo x Whi
#pragma unroll
            for (int tm = 0; tm < 2; tm++)
#pragma unroll
                for (int nt = 0; nt < 4; nt++) {
                    mma16816(acc[tm][nt * 2 + 0], al[tm], wh[nt][0], wh[nt][1]);
                    mma16816(acc[tm][nt * 2 + 1], al[tm], wh[nt][2], wh[nt][3]);
                }
            // batch 3: Ahi x Wlo
#pragma unroll
            for (int tm = 0; tm < 2; tm++)
#pragma unroll
                for (int nt = 0; nt < 4; nt++) {
                    mma16816(acc[tm][nt * 2 + 0], ah[tm], wl[nt][0], wl[nt][1]);
                    mma16816(acc[tm][nt * 2 + 1], ah[tm], wl[nt][2], wl[nt][3]);
                }
        }
        __syncthreads();             // all done reading slot (g&1) before refill
        if (g < 10) {
            loadGroup(g + 2, g & 1);
            CP_COMMIT();
        }
    }

    // epilogue: + bias, relu, split-bf16, store planes
    const int row_in = lane >> 2;
    const int colp = (lane & 3) * 2;
#pragma unroll
    for (int tm = 0; tm < 2; tm++) {
        const int gm = m0 + wm * 32 + tm * 16 + row_in;
#pragma unroll
        for (int j = 0; j < 8; j++) {
            int n = wn * 64 + j * 8 + colp;
            float b0 = __ldg(biasp + n), b1 = __ldg(biasp + n + 1);
            float v0 = fmaxf(acc[tm][j][0] + b0, 0.f);
            float v1 = fmaxf(acc[tm][j][1] + b1, 0.f);
            float v2 = fmaxf(acc[tm][j][2] + b0, 0.f);
            float v3 = fmaxf(acc[tm][j][3] + b1, 0.f);
            uint32_t hi, lo;
            if (gm < N_NODES) {
                split2(v0, v1, hi, lo);
                *(uint32_t*)(OH + (size_t)gm * DIM + n) = hi;
                *(uint32_t*)(OL + (size_t)gm * DIM + n) = lo;
            }
            if (gm + 8 < N_NODES) {
                split2(v2, v3, hi, lo);
                *(uint32_t*)(OH + (size_t)(gm + 8) * DIM + n) = hi;
                *(uint32_t*)(OL + (size_t)(gm + 8) * DIM + n) = lo;
            }
        }
    }
}

// ---------------- classifier ----------------
__global__ void __launch_bounds__(256)
cls_k(const float* __restrict__ Wc, const float* __restrict__ bc,
      float* __restrict__ out)
{
    int gw = (blockIdx.x * blockDim.x + threadIdx.x) >> 5;
    if (gw >= N_NODES) return;
    int lane = threadIdx.x & 31;

    uint2 hu = ((const uint2*)(g_xhi + (size_t)gw * DIM))[lane];
    uint2 lu = ((const uint2*)(g_xlo + (size_t)gw * DIM))[lane];
    float2 p, q;
    p = b22f(hu.x); q = b22f(lu.x);
    float h0 = p.x + q.x, h1 = p.y + q.y;
    p = b22f(hu.y); q = b22f(lu.y);
    float h2 = p.x + q.x, h3 = p.y + q.y;

    int k = lane * 4;
    float p0 = h0 * __ldg(Wc + (k + 0) * 2) + h1 * __ldg(Wc + (k + 1) * 2)
             + h2 * __ldg(Wc + (k + 2) * 2) + h3 * __ldg(Wc + (k + 3) * 2);
    float p1 = h0 * __ldg(Wc + (k + 0) * 2 + 1) + h1 * __ldg(Wc + (k + 1) * 2 + 1)
             + h2 * __ldg(Wc + (k + 2) * 2 + 1) + h3 * __ldg(Wc + (k + 3) * 2 + 1);
#pragma unroll
    for (int d = 16; d > 0; d >>= 1) {
        p0 += __shfl_down_sync(0xffffffffu, p0, d);
        p1 += __shfl_down_sync(0xffffffffu, p1, d);
    }
    if (lane == 0) {
        out[(size_t)gw * 2 + 0] = p0 + __ldg(bc);
        out[(size_t)gw * 2 + 1] = p1 + __ldg(bc + 1);
    }
}

// ---------------- launch ----------------
extern "C" void kernel_launch(void* const* d_in, const int* in_sizes, int n_in,
                              void* d_out, int out_size)
{
    const float* x          = (const float*)d_in[0];
    const int*   edge_index = (const int*)d_in[1];
    const int*   edge_type  = (const int*)d_in[2];
    const float* W_rel1     = (const float*)d_in[3];
    const float* W_root1    = (const float*)d_in[4];
    const float* b1         = (const float*)d_in[5];
    const float* W_rel2     = (const float*)d_in[6];
    const float* W_root2    = (const float*)d_in[7];
    const float* b2         = (const float*)d_in[8];
    const float* Wc         = (const float*)d_in[9];
    const float* bc         = (const float*)d_in[10];
    float* out = (float*)d_out;

    cudaFuncSetAttribute(gemm12_k, cudaFuncAttributeMaxDynamicSharedMemorySize, SMEM_BYTES);

    zero_cnt_k<<<(NB2 + 255) / 256, 256>>>();                              // 1
    placeconv_k<<<(CONV_TOTAL + 255) / 256, 256>>>(edge_index, edge_type,  // 2
                                                   x, W_root1, W_rel1, W_root2, W_rel2);
    // layer 1
    agg_k<<<(N_NODES * 32 + 255) / 256, 256>>>(x, 0);                      // 3
    gemm12_k<<<MT, 256, SMEM_BYTES>>>(b1, 0);                              // 4 (ncu slot)
    // layer 2
    agg_k<<<(N_NODES * 32 + 255) / 256, 256>>>(x, 1);                      // 5
    gemm12_k<<<MT, 256, SMEM_BYTES>>>(b2, 1);                              // 6
    // classifier
    cls_k<<<(N_NODES * 32 + 255) / 256, 256>>>(Wc, bc, out);               // 7
}

// round 15
// speedup vs baseline: 1.0213x; 1.0213x over previous
#include <cuda_runtime.h>
#include <cuda_bf16.h>
#include <cstdint>
#include <cstddef>

#define N_NODES 100000
#define DIM 128
#define N_REL 2
#define N_EDGES 500000
#define NB2 (N_REL * N_NODES)
#define CAP 64
#define MT ((N_NODES + 127) / 128)   // 782 M-tiles

// group slot: Ahi|Alo|Whi|Wlo, each 128 rows x 32 cols bf16, row stride 40 elems (80B, 16B-aligned)
#define SKC 40
#define TILE_E (128 * SKC)                    // 5120 elems = 10240 B per tile
#define SLOT_B (4 * TILE_E * 2)               // 40960 B per group slot
#define NSLOT 2
#define SMEM_BYTES (NSLOT * SLOT_B)           // 81920 B -> 2 CTA/SM

// ---------------- scratch ----------------
__device__ int g_cnti[NB2];
__device__ int g_bkt[(size_t)NB2 * CAP];
__device__ __nv_bfloat16 g_whi[6 * DIM * DIM];          // [w][n][k] transposed, split
__device__ __nv_bfloat16 g_wlo[6 * DIM * DIM];
__device__ __nv_bfloat16 g_xhi[(size_t)N_NODES * DIM];  // x planes; reused for relu(h2)
__device__ __nv_bfloat16 g_xlo[(size_t)N_NODES * DIM];
__device__ __nv_bfloat16 g_hhi[(size_t)N_NODES * DIM];  // relu(h1) planes
__device__ __nv_bfloat16 g_hlo[(size_t)N_NODES * DIM];
__device__ __nv_bfloat16 g_s0hi[(size_t)N_NODES * DIM];
__device__ __nv_bfloat16 g_s0lo[(size_t)N_NODES * DIM];
__device__ __nv_bfloat16 g_s1hi[(size_t)N_NODES * DIM];
__device__ __nv_bfloat16 g_s1lo[(size_t)N_NODES * DIM];

// ---------------- helpers ----------------
__device__ __forceinline__ uint32_t smem_u32(const void* p) {
    uint32_t a;
    asm("{ .reg .u64 t; cvta.to.shared.u64 t, %1; cvt.u32.u64 %0, t; }" : "=r"(a) : "l"(p));
    return a;
}
__device__ __forceinline__ void ldsm_x4(uint32_t* r, uint32_t addr) {
    asm volatile("ldmatrix.sync.aligned.m8n8.x4.shared.b16 {%0,%1,%2,%3}, [%4];"
                 : "=r"(r[0]), "=r"(r[1]), "=r"(r[2]), "=r"(r[3]) : "r"(addr));
}
__device__ __forceinline__ void mma16816(float* c, const uint32_t* a, uint32_t b0, uint32_t b1) {
    asm volatile("mma.sync.aligned.m16n8k16.row.col.f32.bf16.bf16.f32 "
                 "{%0,%1,%2,%3}, {%4,%5,%6,%7}, {%8,%9}, {%0,%1,%2,%3};"
                 : "+f"(c[0]), "+f"(c[1]), "+f"(c[2]), "+f"(c[3])
                 : "r"(a[0]), "r"(a[1]), "r"(a[2]), "r"(a[3]), "r"(b0), "r"(b1));
}
__device__ __forceinline__ void cp8(uint32_t dst, const void* src) {
    asm volatile("cp.async.ca.shared.global [%0], [%1], 8;" :: "r"(dst), "l"(src));
}
#define CP_COMMIT()  asm volatile("cp.async.commit_group;" ::: "memory")
#define CP_WAIT_1()  asm volatile("cp.async.wait_group 1;" ::: "memory")
#define CP_WAIT_0()  asm volatile("cp.async.wait_group 0;" ::: "memory")

__device__ __forceinline__ void split2(float a, float b, uint32_t& hi, uint32_t& lo) {
    __nv_bfloat16 ha = __float2bfloat16(a), hb = __float2bfloat16(b);
    __nv_bfloat16 la = __float2bfloat16(a - __bfloat162float(ha));
    __nv_bfloat16 lb = __float2bfloat16(b - __bfloat162float(hb));
    hi = (uint32_t)__bfloat16_as_ushort(ha) | ((uint32_t)__bfloat16_as_ushort(hb) << 16);
    lo = (uint32_t)__bfloat16_as_ushort(la) | ((uint32_t)__bfloat16_as_ushort(lb) << 16);
}
__device__ __forceinline__ float2 b22f(uint32_t u) {
    __nv_bfloat162 b = *reinterpret_cast<__nv_bfloat162*>(&u);
    return __bfloat1622float2(b);
}

// ---------------- CSR zero ----------------
__global__ void zero_cnt_k() {
    int i = blockIdx.x * blockDim.x + threadIdx.x;
    if (i < NB2) g_cnti[i] = 0;
}

// ---------------- fused: edge placement + weight/x split conversion ----------
#define CONV_TOTAL (6 * DIM * DIM + N_NODES * DIM)
__global__ void placeconv_k(const int* __restrict__ ei, const int* __restrict__ et,
                            const float* __restrict__ x,
                            const float* __restrict__ Wroot1, const float* __restrict__ Wrel1,
                            const float* __restrict__ Wroot2, const float* __restrict__ Wrel2) {
    int id = blockIdx.x * blockDim.x + threadIdx.x;
    if (id < N_EDGES) {
        int src = ei[id];
        int dst = ei[N_EDGES + id];
        int r = et[id];
        int idx = r * N_NODES + dst;
        int pos = atomicAdd(&g_cnti[idx], 1);
        if (pos < CAP) g_bkt[(size_t)idx * CAP + pos] = src;
    }
    if (id < 6 * DIM * DIM) {
        int w = id >> 14;
        int rem = id & 16383;
        int k = rem >> 7, n = rem & 127;
        float v;
        switch (w) {
            case 0: v = Wroot1[rem]; break;
            case 1: v = Wrel1[rem]; break;
            case 2: v = Wrel1[DIM * DIM + rem]; break;
            case 3: v = Wroot2[rem]; break;
            case 4: v = Wrel2[rem]; break;
            default: v = Wrel2[DIM * DIM + rem]; break;
        }
        __nv_bfloat16 hi = __float2bfloat16(v);
        __nv_bfloat16 lo = __float2bfloat16(v - __bfloat162float(hi));
        size_t dst = (size_t)w * DIM * DIM + (size_t)n * DIM + k;   // transposed [n][k]
        g_whi[dst] = hi;
        g_wlo[dst] = lo;
    }
    size_t id2 = (size_t)id - 6 * DIM * DIM;
    if (id >= 6 * DIM * DIM && id2 < (size_t)N_NODES * DIM) {
        float v = x[id2];
        __nv_bfloat16 hi = __float2bfloat16(v);
        __nv_bfloat16 lo = __float2bfloat16(v - __bfloat162float(hi));
        g_xhi[id2] = hi;
        g_xlo[id2] = lo;
    }
}

// ---------------- pre-aggregation: one warp per (rel,node) pair --------------
// s_r[node] = mean over bucket of features, split-bf16 output.
__global__ void __launch_bounds__(256)
agg_k(const float* __restrict__ xf, int layer)
{
    int idx = (blockIdx.x * blockDim.x + threadIdx.x) >> 5;   // 0..NB2-1
    if (idx >= NB2) return;
    int lane = threadIdx.x & 31;
    int node = (idx >= N_NODES) ? (idx - N_NODES) : idx;

    int cnt = g_cnti[idx];
    int n = min(cnt, CAP);
    const int* bkt = g_bkt + (size_t)idx * CAP;
    float s0 = 0.f, s1 = 0.f, s2 = 0.f, s3 = 0.f;
    if (layer == 0) {
        int j = 0;
        for (; j + 2 <= n; j += 2) {
            int a = bkt[j], b = bkt[j + 1];
            float4 va = ((const float4*)(xf + (size_t)a * DIM))[lane];
            float4 vb = ((const float4*)(xf + (size_t)b * DIM))[lane];
            s0 += va.x + vb.x; s1 += va.y + vb.y;
            s2 += va.z + vb.z; s3 += va.w + vb.w;
        }
        if (j < n) {
            float4 va = ((const float4*)(xf + (size_t)bkt[j] * DIM))[lane];
            s0 += va.x; s1 += va.y; s2 += va.z; s3 += va.w;
        }
    } else {
        for (int j = 0; j < n; j++) {
            int a = bkt[j];
            uint2 ha = ((const uint2*)(g_hhi + (size_t)a * DIM))[lane];
            uint2 la = ((const uint2*)(g_hlo + (size_t)a * DIM))[lane];
            float2 p, q;
            p = b22f(ha.x); q = b22f(la.x); s0 += p.x + q.x; s1 += p.y + q.y;
            p = b22f(ha.y); q = b22f(la.y); s2 += p.x + q.x; s3 += p.y + q.y;
        }
    }
    float w = cnt ? (1.0f / (float)cnt) : 0.0f;
    uint32_t h01, l01, h23, l23;
    split2(s0 * w, s1 * w, h01, l01);
    split2(s2 * w, s3 * w, h23, l23);
    __nv_bfloat16* shi = (idx >= N_NODES) ? g_s1hi : g_s0hi;
    __nv_bfloat16* slo = (idx >= N_NODES) ? g_s1lo : g_s0lo;
    ((uint2*)(shi + (size_t)node * DIM))[lane] = make_uint2(h01, h23);
    ((uint2*)(slo + (size_t)node * DIM))[lane] = make_uint2(l01, l23);
}

// ---------------- grouped HMMA GEMM: 12 groups of (Ahi,Alo,Whi,Wlo) @ K=32 ---
// h = x@Wroot + s0@W0 + s1@W1 + b with split-bf16: per group all 3 products
// computed from register-held fragments; wlo ldsm hidden under MMA batch.
// 2-slot double buffer, M-tile 128, 256 thr, 8 warps, warp tile 32x64, 2 CTA/SM.
__global__ void __launch_bounds__(256, 2)
gemm12_k(const float* __restrict__ biasp, int layer)
{
    extern __shared__ __nv_bfloat16 sm[];
    const int tid = threadIdx.x;
    const int wid = tid >> 5;
    const int lane = tid & 31;
    const int wm = wid & 3;      // 4 warp rows x 32
    const int wn = wid >> 2;     // 2 warp cols x 64
    const int m0 = blockIdx.x * 128;

    const uint32_t sb = smem_u32(sm);

    const __nv_bfloat16* AHI[3] = { layer ? g_hhi : g_xhi, g_s0hi, g_s1hi };
    const __nv_bfloat16* ALO[3] = { layer ? g_hlo : g_xlo, g_s0lo, g_s1lo };
    const __nv_bfloat16* WH = g_whi + (size_t)(layer * 3) * DIM * DIM;
    const __nv_bfloat16* WL = g_wlo + (size_t)(layer * 3) * DIM * DIM;
    __nv_bfloat16* OH = layer ? g_xhi : g_hhi;
    __nv_bfloat16* OL = layer ? g_xlo : g_hlo;

    // group g: input i = g>>2, K-chunk kc = g&3 (K offset kc*32)
    auto loadGroup = [&](int g, int slot) {
        const int i = g >> 2;
        const int ko = (g & 3) * 32;
        const __nv_bfloat16* pah = AHI[i];
        const __nv_bfloat16* pal = ALO[i];
        const __nv_bfloat16* pwh = WH + (size_t)i * DIM * DIM;
        const __nv_bfloat16* pwl = WL + (size_t)i * DIM * DIM;
        const uint32_t base = sb + (uint32_t)slot * SLOT_B;
#pragma unroll
        for (int it = 0; it < 4; it++) {
            int idx = tid + it * 256;        // 1024: row = idx>>3, c4 = idx&7
            int row = idx >> 3, c4 = idx & 7;
            uint32_t doff = (uint32_t)(row * SKC + c4 * 4) * 2;
            size_t goff = (size_t)row * DIM + ko + c4 * 4;
            int gm = m0 + row;
            if (gm < N_NODES) {
                size_t aoffg = (size_t)gm * DIM + ko + c4 * 4;
                cp8(base + doff, pah + aoffg);
                cp8(base + (uint32_t)TILE_E * 2 + doff, pal + aoffg);
            }
            cp8(base + (uint32_t)TILE_E * 4 + doff, pwh + goff);
            cp8(base + (uint32_t)TILE_E * 6 + doff, pwl + goff);
        }
    };

    // prologue: groups 0, 1
    loadGroup(0, 0); CP_COMMIT();
    loadGroup(1, 1); CP_COMMIT();

    // per-lane ldmatrix offsets (validated layout; smem row stride SKC=40 elems = 80B)
    const int a_r = lane & 15;
    const int a_c = (lane >> 4) << 3;
    const int b_r = (lane & 7) + ((lane >> 4) << 3);
    const int b_c = ((lane >> 3) & 1) << 3;
    const uint32_t aoff = (uint32_t)((wm * 32 + a_r) * SKC + a_c) * 2;
    const uint32_t boff = (uint32_t)((wn * 64 + b_r) * SKC + b_c) * 2;

    float acc[2][8][4] = {};

#pragma unroll 1
    for (int g = 0; g < 12; g++) {
        if (g == 11) { CP_WAIT_0(); } else { CP_WAIT_1(); }
        __syncthreads();             // group g resident; other slot fully consumed

        const uint32_t base = sb + (uint32_t)(g & 1) * SLOT_B;
        const uint32_t sAhi = base;
        const uint32_t sAlo = base + (uint32_t)TILE_E * 2;
        const uint32_t sWhi = base + (uint32_t)TILE_E * 4;
        const uint32_t sWlo = base + (uint32_t)TILE_E * 6;

#pragma unroll
        for (int t = 0; t < 2; t++) {
            const uint32_t k2 = (uint32_t)t * 32;   // 16 elems = 32B per kstep
            uint32_t ah[2][4], al[2][4], wh[4][4], wl[4][4];
            ldsm_x4(ah[0], sAhi + aoff + k2);
            ldsm_x4(ah[1], sAhi + aoff + (uint32_t)(16 * SKC) * 2 + k2);
            ldsm_x4(al[0], sAlo + aoff + k2);
            ldsm_x4(al[1], sAlo + aoff + (uint32_t)(16 * SKC) * 2 + k2);
#pragma unroll
            for (int nt = 0; nt < 4; nt++)
                ldsm_x4(wh[nt], sWhi + boff + (uint32_t)(nt * 16 * SKC) * 2 + k2);
            // batch 1: Ahi x Whi
#pragma unroll
            for (int tm = 0; tm < 2; tm++)
#pragma unroll
                for (int nt = 0; nt < 4; nt++) {
                    mma16816(acc[tm][nt * 2 + 0], ah[tm], wh[nt][0], wh[nt][1]);
                    mma16816(acc[tm][nt * 2 + 1], ah[tm], wh[nt][2], wh[nt][3]);
                }
            // wlo ldsm issued here; latency hidden under batch 2
#pragma unroll
            for (int nt = 0; nt < 4; nt++)
                ldsm_x4(wl[nt], sWlo + boff + (uint32_t)(nt * 16 * SKC) * 2 + k2);
            // batch 2: Alo x Whi
#pragma unroll
            for (int tm = 0; tm < 2; tm++)
#pragma unroll
                for (int nt = 0; nt < 4; nt++) {
                    mma16816(acc[tm][nt * 2 + 0], al[tm], wh[nt][0], wh[nt][1]);
                    mma16816(acc[tm][nt * 2 + 1], al[tm], wh[nt][2], wh[nt][3]);
                }
            // batch 3: Ahi x Wlo
#pragma unroll
            for (int tm = 0; tm < 2; tm++)
#pragma unroll
                for (int nt = 0; nt < 4; nt++) {
                    mma16816(acc[tm][nt * 2 + 0], ah[tm], wl[nt][0], wl[nt][1]);
                    mma16816(acc[tm][nt * 2 + 1], ah[tm], wl[nt][2], wl[nt][3]);
                }
        }
        __syncthreads();             // all done reading slot (g&1) before refill
        if (g < 10) {
            loadGroup(g + 2, g & 1);
            CP_COMMIT();
        }
    }

    // epilogue: + bias, relu, split-bf16, store planes
    const int row_in = lane >> 2;
    const int colp = (lane & 3) * 2;
#pragma unroll
    for (int tm = 0; tm < 2; tm++) {
        const int gm = m0 + wm * 32 + tm * 16 + row_in;
#pragma unroll
        for (int j = 0; j < 8; j++) {
            int n = wn * 64 + j * 8 + colp;
            float b0 = __ldg(biasp + n), b1 = __ldg(biasp + n + 1);
            float v0 = fmaxf(acc[tm][j][0] + b0, 0.f);
            float v1 = fmaxf(acc[tm][j][1] + b1, 0.f);
            float v2 = fmaxf(acc[tm][j][2] + b0, 0.f);
            float v3 = fmaxf(acc[tm][j][3] + b1, 0.f);
            uint32_t hi, lo;
            if (gm < N_NODES) {
                split2(v0, v1, hi, lo);
                *(uint32_t*)(OH + (size_t)gm * DIM + n) = hi;
                *(uint32_t*)(OL + (size_t)gm * DIM + n) = lo;
            }
            if (gm + 8 < N_NODES) {
                split2(v2, v3, hi, lo);
                *(uint32_t*)(OH + (size_t)(gm + 8) * DIM + n) = hi;
                *(uint32_t*)(OL + (size_t)(gm + 8) * DIM + n) = lo;
            }
        }
    }
}

// ---------------- classifier ----------------
__global__ void __launch_bounds__(256)
cls_k(const float* __restrict__ Wc, const float* __restrict__ bc,
      float* __restrict__ out)
{
    int gw = (blockIdx.x * blockDim.x + threadIdx.x) >> 5;
    if (gw >= N_NODES) return;
    int lane = threadIdx.x & 31;

    uint2 hu = ((const uint2*)(g_xhi + (size_t)gw * DIM))[lane];
    uint2 lu = ((const uint2*)(g_xlo + (size_t)gw * DIM))[lane];
    float2 p, q;
    p = b22f(hu.x); q = b22f(lu.x);
    float h0 = p.x + q.x, h1 = p.y + q.y;
    p = b22f(hu.y); q = b22f(lu.y);
    float h2 = p.x + q.x, h3 = p.y + q.y;

    int k = lane * 4;
    float p0 = h0 * __ldg(Wc + (k + 0) * 2) + h1 * __ldg(Wc + (k + 1) * 2)
             + h2 * __ldg(Wc + (k + 2) * 2) + h3 * __ldg(Wc + (k + 3) * 2);
    float p1 = h0 * __ldg(Wc + (k + 0) * 2 + 1) + h1 * __ldg(Wc + (k + 1) * 2 + 1)
             + h2 * __ldg(Wc + (k + 2) * 2 + 1) + h3 * __ldg(Wc + (k + 3) * 2 + 1);
#pragma unroll
    for (int d = 16; d > 0; d >>= 1) {
        p0 += __shfl_down_sync(0xffffffffu, p0, d);
        p1 += __shfl_down_sync(0xffffffffu, p1, d);
    }
    if (lane == 0) {
        out[(size_t)gw * 2 + 0] = p0 + __ldg(bc);
        out[(size_t)gw * 2 + 1] = p1 + __ldg(bc + 1);
    }
}

// ---------------- launch ----------------
extern "C" void kernel_launch(void* const* d_in, const int* in_sizes, int n_in,
                              void* d_out, int out_size)
{
    const float* x          = (const float*)d_in[0];
    const int*   edge_index = (const int*)d_in[1];
    const int*   edge_type  = (const int*)d_in[2];
    const float* W_rel1     = (const float*)d_in[3];
    const float* W_root1    = (const float*)d_in[4];
    const float* b1         = (const float*)d_in[5];
    const float* W_rel2     = (const float*)d_in[6];
    const float* W_root2    = (const float*)d_in[7];
    const float* b2         = (const float*)d_in[8];
    const float* Wc         = (const float*)d_in[9];
    const float* bc         = (const float*)d_in[10];
    float* out = (float*)d_out;

    cudaFuncSetAttribute(gemm12_k, cudaFuncAttributeMaxDynamicSharedMemorySize, SMEM_BYTES);

    zero_cnt_k<<<(NB2 + 255) / 256, 256>>>();                              // 1
    placeconv_k<<<(CONV_TOTAL + 255) / 256, 256>>>(edge_index, edge_type,  // 2
                                                   x, W_root1, W_rel1, W_root2, W_rel2);
    // layer 1
    agg_k<<<(NB2 * 32 + 255) / 256, 256>>>(x, 0);                          // 3
    gemm12_k<<<MT, 256, SMEM_BYTES>>>(b1, 0);                              // 4 (ncu slot)
    // layer 2
    agg_k<<<(NB2 * 32 + 255) / 256, 256>>>(x, 1);                          // 5
    gemm12_k<<<MT, 256, SMEM_BYTES>>>(b2, 1);                              // 6
    // classifier
    cls_k<<<(N_NODES * 32 + 255) / 256, 256>>>(Wc, bc, out);               // 7
}

// round 16
// speedup vs baseline: 1.1714x; 1.1469x over previous
#include <cuda_runtime.h>
#include <cuda_bf16.h>
#include <cstdint>
#include <cstddef>

#define N_NODES 100000
#define DIM 128
#define N_REL 2
#define N_EDGES 500000
#define NB2 (N_REL * N_NODES)
#define CAP 64
#define MT ((N_NODES + 127) / 128)   // 782 M-tiles

// group slot: Ahi|Alo|Whi|Wlo, each 128 rows x 32 cols bf16, row stride 40 elems (80B, 16B-aligned)
#define SKC 40
#define TILE_E (128 * SKC)                    // 5120 elems = 10240 B per tile
#define SLOT_B (4 * TILE_E * 2)               // 40960 B per group slot
#define NSLOT 2
#define SMEM_BYTES (NSLOT * SLOT_B)           // 81920 B -> 2 CTA/SM

// ---------------- scratch ----------------
__device__ int g_cnti[NB2];
__device__ int g_bkt[(size_t)NB2 * CAP];
__device__ __nv_bfloat16 g_whi[6 * DIM * DIM];          // [w][n][k] transposed, split
__device__ __nv_bfloat16 g_wlo[6 * DIM * DIM];
__device__ __nv_bfloat16 g_xhi[(size_t)N_NODES * DIM];  // x planes
__device__ __nv_bfloat16 g_xlo[(size_t)N_NODES * DIM];
__device__ __nv_bfloat16 g_hhi[(size_t)N_NODES * DIM];  // relu(h1) planes
__device__ __nv_bfloat16 g_hlo[(size_t)N_NODES * DIM];
__device__ __nv_bfloat16 g_s0hi[(size_t)N_NODES * DIM];
__device__ __nv_bfloat16 g_s0lo[(size_t)N_NODES * DIM];
__device__ __nv_bfloat16 g_s1hi[(size_t)N_NODES * DIM];
__device__ __nv_bfloat16 g_s1lo[(size_t)N_NODES * DIM];

// ---------------- helpers ----------------
__device__ __forceinline__ uint32_t smem_u32(const void* p) {
    uint32_t a;
    asm("{ .reg .u64 t; cvta.to.shared.u64 t, %1; cvt.u32.u64 %0, t; }" : "=r"(a) : "l"(p));
    return a;
}
__device__ __forceinline__ void ldsm_x4(uint32_t* r, uint32_t addr) {
    asm volatile("ldmatrix.sync.aligned.m8n8.x4.shared.b16 {%0,%1,%2,%3}, [%4];"
                 : "=r"(r[0]), "=r"(r[1]), "=r"(r[2]), "=r"(r[3]) : "r"(addr));
}
__device__ __forceinline__ void mma16816(float* c, const uint32_t* a, uint32_t b0, uint32_t b1) {
    asm volatile("mma.sync.aligned.m16n8k16.row.col.f32.bf16.bf16.f32 "
                 "{%0,%1,%2,%3}, {%4,%5,%6,%7}, {%8,%9}, {%0,%1,%2,%3};"
                 : "+f"(c[0]), "+f"(c[1]), "+f"(c[2]), "+f"(c[3])
                 : "r"(a[0]), "r"(a[1]), "r"(a[2]), "r"(a[3]), "r"(b0), "r"(b1));
}
__device__ __forceinline__ void cp8(uint32_t dst, const void* src) {
    asm volatile("cp.async.ca.shared.global [%0], [%1], 8;" :: "r"(dst), "l"(src));
}
#define CP_COMMIT()  asm volatile("cp.async.commit_group;" ::: "memory")
#define CP_WAIT_1()  asm volatile("cp.async.wait_group 1;" ::: "memory")
#define CP_WAIT_0()  asm volatile("cp.async.wait_group 0;" ::: "memory")

__device__ __forceinline__ void split2(float a, float b, uint32_t& hi, uint32_t& lo) {
    __nv_bfloat16 ha = __float2bfloat16(a), hb = __float2bfloat16(b);
    __nv_bfloat16 la = __float2bfloat16(a - __bfloat162float(ha));
    __nv_bfloat16 lb = __float2bfloat16(b - __bfloat162float(hb));
    hi = (uint32_t)__bfloat16_as_ushort(ha) | ((uint32_t)__bfloat16_as_ushort(hb) << 16);
    lo = (uint32_t)__bfloat16_as_ushort(la) | ((uint32_t)__bfloat16_as_ushort(lb) << 16);
}
__device__ __forceinline__ float2 b22f(uint32_t u) {
    __nv_bfloat162 b = *reinterpret_cast<__nv_bfloat162*>(&u);
    return __bfloat1622float2(b);
}

// ---------------- CSR zero ----------------
__global__ void zero_cnt_k() {
    int i = blockIdx.x * blockDim.x + threadIdx.x;
    if (i < NB2) g_cnti[i] = 0;
}

// ---------------- fused: edge placement + weight/x split conversion ----------
#define CONV_TOTAL (6 * DIM * DIM + N_NODES * DIM)
__global__ void placeconv_k(const int* __restrict__ ei, const int* __restrict__ et,
                            const float* __restrict__ x,
                            const float* __restrict__ Wroot1, const float* __restrict__ Wrel1,
                            const float* __restrict__ Wroot2, const float* __restrict__ Wrel2) {
    int id = blockIdx.x * blockDim.x + threadIdx.x;
    if (id < N_EDGES) {
        int src = ei[id];
        int dst = ei[N_EDGES + id];
        int r = et[id];
        int idx = r * N_NODES + dst;
        int pos = atomicAdd(&g_cnti[idx], 1);
        if (pos < CAP) g_bkt[(size_t)idx * CAP + pos] = src;
    }
    if (id < 6 * DIM * DIM) {
        int w = id >> 14;
        int rem = id & 16383;
        int k = rem >> 7, n = rem & 127;
        float v;
        switch (w) {
            case 0: v = Wroot1[rem]; break;
            case 1: v = Wrel1[rem]; break;
            case 2: v = Wrel1[DIM * DIM + rem]; break;
            case 3: v = Wroot2[rem]; break;
            case 4: v = Wrel2[rem]; break;
            default: v = Wrel2[DIM * DIM + rem]; break;
        }
        __nv_bfloat16 hi = __float2bfloat16(v);
        __nv_bfloat16 lo = __float2bfloat16(v - __bfloat162float(hi));
        size_t dst = (size_t)w * DIM * DIM + (size_t)n * DIM + k;   // transposed [n][k]
        g_whi[dst] = hi;
        g_wlo[dst] = lo;
    }
    size_t id2 = (size_t)id - 6 * DIM * DIM;
    if (id >= 6 * DIM * DIM && id2 < (size_t)N_NODES * DIM) {
        float v = x[id2];
        __nv_bfloat16 hi = __float2bfloat16(v);
        __nv_bfloat16 lo = __float2bfloat16(v - __bfloat162float(hi));
        g_xhi[id2] = hi;
        g_xlo[id2] = lo;
    }
}

// ---------------- pre-aggregation: s_r = mean_r(features), split-bf16 out ----
// (R13-proven form: one warp per node, serial 2-relation loop)
__global__ void __launch_bounds__(256)
agg_k(const float* __restrict__ xf, int layer)
{
    int gw = (blockIdx.x * blockDim.x + threadIdx.x) >> 5;
    if (gw >= N_NODES) return;
    int lane = threadIdx.x & 31;

#pragma unroll
    for (int r = 0; r < 2; r++) {
        int idx = r * N_NODES + gw;
        int cnt = g_cnti[idx];
        int n = min(cnt, CAP);
        const int* bkt = g_bkt + (size_t)idx * CAP;
        float s0 = 0.f, s1 = 0.f, s2 = 0.f, s3 = 0.f;
        if (layer == 0) {
            int j = 0;
            for (; j + 2 <= n; j += 2) {
                int a = bkt[j], b = bkt[j + 1];
                float4 va = ((const float4*)(xf + (size_t)a * DIM))[lane];
                float4 vb = ((const float4*)(xf + (size_t)b * DIM))[lane];
                s0 += va.x + vb.x; s1 += va.y + vb.y;
                s2 += va.z + vb.z; s3 += va.w + vb.w;
            }
            if (j < n) {
                float4 va = ((const float4*)(xf + (size_t)bkt[j] * DIM))[lane];
                s0 += va.x; s1 += va.y; s2 += va.z; s3 += va.w;
            }
        } else {
            for (int j = 0; j < n; j++) {
                int a = bkt[j];
                uint2 ha = ((const uint2*)(g_hhi + (size_t)a * DIM))[lane];
                uint2 la = ((const uint2*)(g_hlo + (size_t)a * DIM))[lane];
                float2 p, q;
                p = b22f(ha.x); q = b22f(la.x); s0 += p.x + q.x; s1 += p.y + q.y;
                p = b22f(ha.y); q = b22f(la.y); s2 += p.x + q.x; s3 += p.y + q.y;
            }
        }
        float w = cnt ? (1.0f / (float)cnt) : 0.0f;
        uint32_t h01, l01, h23, l23;
        split2(s0 * w, s1 * w, h01, l01);
        split2(s2 * w, s3 * w, h23, l23);
        __nv_bfloat16* shi = r ? g_s1hi : g_s0hi;
        __nv_bfloat16* slo = r ? g_s1lo : g_s0lo;
        ((uint2*)(shi + (size_t)gw * DIM))[lane] = make_uint2(h01, h23);
        ((uint2*)(slo + (size_t)gw * DIM))[lane] = make_uint2(l01, l23);
    }
}

// ---------------- grouped HMMA GEMM + fused classifier (layer 1) ------------
// h = x@Wroot + s0@W0 + s1@W1 + b.  layer 0 epilogue: relu + split planes.
// layer 1 epilogue: logits = relu(h)@Wc + bc written directly (no h2 planes).
__global__ void __launch_bounds__(256, 2)
gemm12_k(const float* __restrict__ biasp, int layer,
         const float* __restrict__ Wc, const float* __restrict__ bc,
         float* __restrict__ out)
{
    extern __shared__ __nv_bfloat16 sm[];
    const int tid = threadIdx.x;
    const int wid = tid >> 5;
    const int lane = tid & 31;
    const int wm = wid & 3;      // 4 warp rows x 32
    const int wn = wid >> 2;     // 2 warp cols x 64
    const int m0 = blockIdx.x * 128;

    const uint32_t sb = smem_u32(sm);

    const __nv_bfloat16* AHI[3] = { layer ? g_hhi : g_xhi, g_s0hi, g_s1hi };
    const __nv_bfloat16* ALO[3] = { layer ? g_hlo : g_xlo, g_s0lo, g_s1lo };
    const __nv_bfloat16* WH = g_whi + (size_t)(layer * 3) * DIM * DIM;
    const __nv_bfloat16* WL = g_wlo + (size_t)(layer * 3) * DIM * DIM;

    // group g: input i = g>>2, K-chunk kc = g&3 (K offset kc*32)
    auto loadGroup = [&](int g, int slot) {
        const int i = g >> 2;
        const int ko = (g & 3) * 32;
        const __nv_bfloat16* pah = AHI[i];
        const __nv_bfloat16* pal = ALO[i];
        const __nv_bfloat16* pwh = WH + (size_t)i * DIM * DIM;
        const __nv_bfloat16* pwl = WL + (size_t)i * DIM * DIM;
        const uint32_t base = sb + (uint32_t)slot * SLOT_B;
#pragma unroll
        for (int it = 0; it < 4; it++) {
            int idx = tid + it * 256;        // 1024: row = idx>>3, c4 = idx&7
            int row = idx >> 3, c4 = idx & 7;
            uint32_t doff = (uint32_t)(row * SKC + c4 * 4) * 2;
            size_t goff = (size_t)row * DIM + ko + c4 * 4;
            int gm = m0 + row;
            if (gm < N_NODES) {
                size_t aoffg = (size_t)gm * DIM + ko + c4 * 4;
                cp8(base + doff, pah + aoffg);
                cp8(base + (uint32_t)TILE_E * 2 + doff, pal + aoffg);
            }
            cp8(base + (uint32_t)TILE_E * 4 + doff, pwh + goff);
            cp8(base + (uint32_t)TILE_E * 6 + doff, pwl + goff);
        }
    };

    // prologue: groups 0, 1
    loadGroup(0, 0); CP_COMMIT();
    loadGroup(1, 1); CP_COMMIT();

    // per-lane ldmatrix offsets (validated layout; smem row stride SKC=40 elems = 80B)
    const int a_r = lane & 15;
    const int a_c = (lane >> 4) << 3;
    const int b_r = (lane & 7) + ((lane >> 4) << 3);
    const int b_c = ((lane >> 3) & 1) << 3;
    const uint32_t aoff = (uint32_t)((wm * 32 + a_r) * SKC + a_c) * 2;
    const uint32_t boff = (uint32_t)((wn * 64 + b_r) * SKC + b_c) * 2;

    float acc[2][8][4] = {};

#pragma unroll 1
    for (int g = 0; g < 12; g++) {
        if (g == 11) { CP_WAIT_0(); } else { CP_WAIT_1(); }
        __syncthreads();             // group g resident; other slot fully consumed

        const uint32_t base = sb + (uint32_t)(g & 1) * SLOT_B;
        const uint32_t sAhi = base;
        const uint32_t sAlo = base + (uint32_t)TILE_E * 2;
        const uint32_t sWhi = base + (uint32_t)TILE_E * 4;
        const uint32_t sWlo = base + (uint32_t)TILE_E * 6;

#pragma unroll
        for (int t = 0; t < 2; t++) {
            const uint32_t k2 = (uint32_t)t * 32;   // 16 elems = 32B per kstep
            uint32_t ah[2][4], al[2][4], wh[4][4], wl[4][4];
            ldsm_x4(ah[0], sAhi + aoff + k2);
            ldsm_x4(ah[1], sAhi + aoff + (uint32_t)(16 * SKC) * 2 + k2);
            ldsm_x4(al[0], sAlo + aoff + k2);
            ldsm_x4(al[1], sAlo + aoff + (uint32_t)(16 * SKC) * 2 + k2);
#pragma unroll
            for (int nt = 0; nt < 4; nt++)
                ldsm_x4(wh[nt], sWhi + boff + (uint32_t)(nt * 16 * SKC) * 2 + k2);
            // batch 1: Ahi x Whi
#pragma unroll
            for (int tm = 0; tm < 2; tm++)
#pragma unroll
                for (int nt = 0; nt < 4; nt++) {
                    mma16816(acc[tm][nt * 2 + 0], ah[tm], wh[nt][0], wh[nt][1]);
                    mma16816(acc[tm][nt * 2 + 1], ah[tm], wh[nt][2], wh[nt][3]);
                }
            // wlo ldsm issued here; latency hidden under batch 2
#pragma unroll
            for (int nt = 0; nt < 4; nt++)
                ldsm_x4(wl[nt], sWlo + boff + (uint32_t)(nt * 16 * SKC) * 2 + k2);
            // batch 2: Alo x Whi
#pragma unroll
            for (int tm = 0; tm < 2; tm++)
#pragma unroll
                for (int nt = 0; nt < 4; nt++) {
                    mma16816(acc[tm][nt * 2 + 0], al[tm], wh[nt][0], wh[nt][1]);
                    mma16816(acc[tm][nt * 2 + 1], al[tm], wh[nt][2], wh[nt][3]);
                }
            // batch 3: Ahi x Wlo
#pragma unroll
            for (int tm = 0; tm < 2; tm++)
#pragma unroll
                for (int nt = 0; nt < 4; nt++) {
                    mma16816(acc[tm][nt * 2 + 0], ah[tm], wl[nt][0], wl[nt][1]);
                    mma16816(acc[tm][nt * 2 + 1], ah[tm], wl[nt][2], wl[nt][3]);
                }
        }
        __syncthreads();             // all done reading slot (g&1) before refill
        if (g < 10) {
            loadGroup(g + 2, g & 1);
            CP_COMMIT();
        }
    }

    const int row_in = lane >> 2;
    const int colp = (lane & 3) * 2;

    if (layer == 0) {
        // epilogue: + bias, relu, split-bf16, store planes
#pragma unroll
        for (int tm = 0; tm < 2; tm++) {
            const int gm = m0 + wm * 32 + tm * 16 + row_in;
#pragma unroll
            for (int j = 0; j < 8; j++) {
                int n = wn * 64 + j * 8 + colp;
                float b0 = __ldg(biasp + n), b1 = __ldg(biasp + n + 1);
                float v0 = fmaxf(acc[tm][j][0] + b0, 0.f);
                float v1 = fmaxf(acc[tm][j][1] + b1, 0.f);
                float v2 = fmaxf(acc[tm][j][2] + b0, 0.f);
                float v3 = fmaxf(acc[tm][j][3] + b1, 0.f);
                uint32_t hi, lo;
                if (gm < N_NODES) {
                    split2(v0, v1, hi, lo);
                    *(uint32_t*)(g_hhi + (size_t)gm * DIM + n) = hi;
                    *(uint32_t*)(g_hlo + (size_t)gm * DIM + n) = lo;
                }
                if (gm + 8 < N_NODES) {
                    split2(v2, v3, hi, lo);
                    *(uint32_t*)(g_hhi + (size_t)(gm + 8) * DIM + n) = hi;
                    *(uint32_t*)(g_hlo + (size_t)(gm + 8) * DIM + n) = lo;
                }
            }
        }
    } else {
        // fused classifier: logits = relu(h2) @ Wc + bc, no h2 materialization.
        // per thread: 4 rows (tm x {0,+8}), 16 of the 128 cols.
        float pr[4][2] = {};
#pragma unroll
        for (int tm = 0; tm < 2; tm++) {
#pragma unroll
            for (int j = 0; j < 8; j++) {
                int n = wn * 64 + j * 8 + colp;
                float b0 = __ldg(biasp + n), b1 = __ldg(biasp + n + 1);
                float wc00 = __ldg(Wc + n * 2),       wc01 = __ldg(Wc + n * 2 + 1);
                float wc10 = __ldg(Wc + (n + 1) * 2), wc11 = __ldg(Wc + (n + 1) * 2 + 1);
                float v0 = fmaxf(acc[tm][j][0] + b0, 0.f);
                float v1 = fmaxf(acc[tm][j][1] + b1, 0.f);
                float v2 = fmaxf(acc[tm][j][2] + b0, 0.f);
                float v3 = fmaxf(acc[tm][j][3] + b1, 0.f);
                pr[tm * 2 + 0][0] += v0 * wc00 + v1 * wc10;
                pr[tm * 2 + 0][1] += v0 * wc01 + v1 * wc11;
                pr[tm * 2 + 1][0] += v2 * wc00 + v3 * wc10;
                pr[tm * 2 + 1][1] += v2 * wc01 + v3 * wc11;
            }
        }
        // quad reduction: lanes q*4+{0..3} hold the same rows
#pragma unroll
        for (int rr = 0; rr < 4; rr++) {
#pragma unroll
            for (int l = 0; l < 2; l++) {
                pr[rr][l] += __shfl_xor_sync(0xffffffffu, pr[rr][l], 1);
                pr[rr][l] += __shfl_xor_sync(0xffffffffu, pr[rr][l], 2);
            }
        }
        __syncthreads();   // slots idle now; reuse smem as reduction buffer
        float* buf = (float*)sm;    // [128 rows][2 logits][2 wn]
        if ((lane & 3) == 0) {
#pragma unroll
            for (int tm = 0; tm < 2; tm++) {
#pragma unroll
                for (int dr = 0; dr < 2; dr++) {
                    int row = wm * 32 + tm * 16 + row_in + dr * 8;
                    buf[(row * 2 + 0) * 2 + wn] = pr[tm * 2 + dr][0];
                    buf[(row * 2 + 1) * 2 + wn] = pr[tm * 2 + dr][1];
                }
            }
        }
        __syncthreads();
        // 256 threads -> 128 rows x 2 logits
        int row = tid >> 1, l = tid & 1;
        int gm = m0 + row;
        if (gm < N_NODES)
            out[(size_t)gm * 2 + l] =
                buf[(row * 2 + l) * 2 + 0] + buf[(row * 2 + l) * 2 + 1] + __ldg(bc + l);
    }
}

// ---------------- launch ----------------
extern "C" void kernel_launch(void* const* d_in, const int* in_sizes, int n_in,
                              void* d_out, int out_size)
{
    const float* x          = (const float*)d_in[0];
    const int*   edge_index = (const int*)d_in[1];
    const int*   edge_type  = (const int*)d_in[2];
    const float* W_rel1     = (const float*)d_in[3];
    const float* W_root1    = (const float*)d_in[4];
    const float* b1         = (const float*)d_in[5];
    const float* W_rel2     = (const float*)d_in[6];
    const float* W_root2    = (const float*)d_in[7];
    const float* b2         = (const float*)d_in[8];
    const float* Wc         = (const float*)d_in[9];
    const float* bc         = (const float*)d_in[10];
    float* out = (float*)d_out;

    cudaFuncSetAttribute(gemm12_k, cudaFuncAttributeMaxDynamicSharedMemorySize, SMEM_BYTES);

    zero_cnt_k<<<(NB2 + 255) / 256, 256>>>();                              // 1
    placeconv_k<<<(CONV_TOTAL + 255) / 256, 256>>>(edge_index, edge_type,  // 2
                                                   x, W_root1, W_rel1, W_root2, W_rel2);
    // layer 1
    agg_k<<<(N_NODES * 32 + 255) / 256, 256>>>(x, 0);                      // 3
    gemm12_k<<<MT, 256, SMEM_BYTES>>>(b1, 0, Wc, bc, nullptr);             // 4 (ncu slot)
    // layer 2 + fused classifier
    agg_k<<<(N_NODES * 32 + 255) / 256, 256>>>(x, 1);                      // 5
    gemm12_k<<<MT, 256, SMEM_BYTES>>>(b2, 1, Wc, bc, out);                 // 6
}